// round 15
// baseline (speedup 1.0000x reference)
#include <cuda_runtime.h>
#include <cstdint>

#define D 128
#define NN_MAX 50000
#define NGRAPH 64
#define NCLASS 16

// ---------------- device scratch (allocation-free) ----------------
__device__ __align__(256) float g_h [NN_MAX * D];
__device__ __align__(256) float g_t [NN_MAX * D];
__device__ __align__(256) float g_m [NN_MAX * D];
__device__ __align__(256) float g_z [NN_MAX * D];
__device__ __align__(256) float g_r [NN_MAX * D];
__device__ __align__(256) float g_ci[NN_MAX * D];
__device__ __align__(256) float g_g [NN_MAX * D];
__device__ __align__(256) float g_cb[3 * D];     // combined biases: z, r, h
__device__ __align__(256) float g_pmax[NGRAPH * D];
__device__ __align__(256) float g_psum[NGRAPH * D];
__device__ __align__(256) float g_cnt [NGRAPH];

__device__ __forceinline__ float sigf(float x) { return 1.0f / (1.0f + __expf(-x)); }

__device__ __forceinline__ uint32_t to_tf32(float f) {
    uint32_t u;
    asm("cvt.rna.tf32.f32 %0, %1;" : "=r"(u) : "f"(f));
    return u;
}

// ---------------- fused multi-output TF32 tensor-core GEMM ----------------
// M=64 tiles; full-K A staged ONCE per CTA; W staged in 64-k-row chunks (2 rounds/output).
// modes: 0: out = acc (+bias)   1: out = sigmoid(acc + aux1[idx])
//        2: r = sigmoid(acc+aux1[idx]); out = r*aux2[idx]
//        3: out[idx] += acc     4: g2 = acc+bias[col]; out = aux2*(aux1*sigf(g2)) + (1-aux2)*out
//        5: out = relu(acc + bias)
struct GemmOut {
    const float* W;
    const float* bias;
    const float* aux1;
    const float* aux2;
    float* out;
    int mode;
};
struct GemmParams { GemmOut o[3]; };

__device__ __forceinline__ void epi_apply(const GemmOut& o, size_t idx, int col, float v) {
    switch (o.mode) {
    case 0: if (o.bias) v += o.bias[col]; o.out[idx] = v; break;
    case 1: o.out[idx] = sigf(v + o.aux1[idx]); break;
    case 2: { float r = sigf(v + o.aux1[idx]); o.out[idx] = r * o.aux2[idx]; } break;
    case 3: o.out[idx] += v; break;
    case 4: { float g2 = v + o.bias[col]; float g1 = o.aux1[idx]; float zz = o.aux2[idx];
              o.out[idx] = zz * (g1 * sigf(g2)) + (1.f - zz) * o.out[idx]; } break;
    case 5: v += o.bias[col]; o.out[idx] = fmaxf(v, 0.f); break;
    }
}

#define MMA_TF32(c, a, b) \
    asm volatile("mma.sync.aligned.m16n8k8.row.col.f32.tf32.tf32.f32 " \
        "{%0,%1,%2,%3}, {%4,%5,%6,%7}, {%8,%9}, {%0,%1,%2,%3};" \
        : "+f"((c)[0]), "+f"((c)[1]), "+f"((c)[2]), "+f"((c)[3]) \
        : "r"((a)[0]), "r"((a)[1]), "r"((a)[2]), "r"((a)[3]), "r"((b)[0]), "r"((b)[1]))

#define AS_STRIDE 132
#define BS_STRIDE 132
#define AS_WORDS (64 * AS_STRIDE)
#define BS_WORDS (64 * BS_STRIDE)
#define GEMM_SMEM_BYTES ((AS_WORDS + BS_WORDS) * 4)   // 67,584 bytes

template<int NOUT>
__global__ void __launch_bounds__(256) gemm_fused(const float* __restrict__ A, GemmParams p, int N)
{
    extern __shared__ uint32_t smem[];
    uint32_t (*As)[AS_STRIDE] = (uint32_t (*)[AS_STRIDE])smem;             // [64][132] full-K
    uint32_t (*Bs)[BS_STRIDE] = (uint32_t (*)[BS_STRIDE])(smem + AS_WORDS);// [64][132]

    const int tid  = threadIdx.x;
    const int lane = tid & 31;
    const int wid  = tid >> 5;
    const int wm   = wid >> 2;          // 0..1 -> m offset wm*32
    const int wn   = wid & 3;           // 0..3 -> n offset wn*32
    const int row0 = blockIdx.x * 64;
    const int gid  = lane >> 2;         // groupID 0..7
    const int tig  = lane & 3;          // thread-in-group 0..3

    // ---- stage full-K A once per CTA: 64 rows x 128 cols = 2048 float4, 8 per thread ----
#pragma unroll
    for (int i = 0; i < 8; i++) {
        int f = tid + i * 256;              // 0..2047
        int r = f >> 5, kg = (f & 31) * 4;  // r 0..63, kg 0..124
        int grow = row0 + r;
        float4 v = make_float4(0.f, 0.f, 0.f, 0.f);
        if (grow < N) v = *(const float4*)&A[(size_t)grow * D + kg];
        As[r][kg + 0] = to_tf32(v.x); As[r][kg + 1] = to_tf32(v.y);
        As[r][kg + 2] = to_tf32(v.z); As[r][kg + 3] = to_tf32(v.w);
    }

    for (int o = 0; o < NOUT; o++) {
        const float* __restrict__ W = p.o[o].W;
        float acc[2][4][4];             // [mfrag][nfrag][reg]
#pragma unroll
        for (int mf = 0; mf < 2; mf++)
#pragma unroll
            for (int nf = 0; nf < 4; nf++)
#pragma unroll
                for (int q = 0; q < 4; q++) acc[mf][nf][q] = 0.f;

#pragma unroll
        for (int kc = 0; kc < D; kc += 64) {
            // W chunk: 64 k-rows x 128 n  (2048 float4; 8 per thread), k-major as-is
#pragma unroll
            for (int i = 0; i < 8; i++) {
                int f = tid + i * 256;
                int k = f >> 5, ng = (f & 31) * 4;
                float4 v = *(const float4*)&W[(size_t)(kc + k) * D + ng];
                Bs[k][ng + 0] = to_tf32(v.x); Bs[k][ng + 1] = to_tf32(v.y);
                Bs[k][ng + 2] = to_tf32(v.z); Bs[k][ng + 3] = to_tf32(v.w);
            }
            __syncthreads();

#pragma unroll
            for (int k8 = 0; k8 < 8; k8++) {
                const int kb = kc + k8 * 8;
                uint32_t af[2][4];
#pragma unroll
                for (int mf = 0; mf < 2; mf++) {
                    int r = wm * 32 + mf * 16 + gid;
                    af[mf][0] = As[r][kb + tig];
                    af[mf][1] = As[r + 8][kb + tig];
                    af[mf][2] = As[r][kb + tig + 4];
                    af[mf][3] = As[r + 8][kb + tig + 4];
                }
                uint32_t bf[4][2];
#pragma unroll
                for (int nf = 0; nf < 4; nf++) {
                    int n = wn * 32 + nf * 8 + gid;
                    bf[nf][0] = Bs[k8 * 8 + tig][n];
                    bf[nf][1] = Bs[k8 * 8 + tig + 4][n];
                }
#pragma unroll
                for (int mf = 0; mf < 2; mf++)
#pragma unroll
                    for (int nf = 0; nf < 4; nf++)
                        MMA_TF32(acc[mf][nf], af[mf], bf[nf]);
            }
            __syncthreads();
        }

        // epilogue
        const GemmOut& po = p.o[o];
#pragma unroll
        for (int mf = 0; mf < 2; mf++) {
            int ra = row0 + wm * 32 + mf * 16 + gid;
            int rb = ra + 8;
#pragma unroll
            for (int nf = 0; nf < 4; nf++) {
                int c0 = wn * 32 + nf * 8 + tig * 2;
                if (ra < N) {
                    epi_apply(po, (size_t)ra * D + c0,     c0,     acc[mf][nf][0]);
                    epi_apply(po, (size_t)ra * D + c0 + 1, c0 + 1, acc[mf][nf][1]);
                }
                if (rb < N) {
                    epi_apply(po, (size_t)rb * D + c0,     c0,     acc[mf][nf][2]);
                    epi_apply(po, (size_t)rb * D + c0 + 1, c0 + 1, acc[mf][nf][3]);
                }
            }
        }
        if (o + 1 < NOUT) __syncthreads();
    }
}

// ---------------- small kernels ----------------
__global__ void combine_bias_kernel(
    const float* bzm, const float* bzs, const float* bias_z,
    const float* brm, const float* brs, const float* bias_r,
    const float* bhm, const float* bhs, const float* bias_h, float* cb) {
    int i = threadIdx.x;
    cb[i]         = bzm[i] + bzs[i] + bias_z[i];
    cb[D + i]     = brm[i] + brs[i] + bias_r[i];
    cb[2 * D + i] = bhm[i] + bhs[i] + bias_h[i];
}

__global__ void copy_kernel(const float* __restrict__ src, float* __restrict__ dst, int n4) {
    int i = blockIdx.x * blockDim.x + threadIdx.x;
    if (i < n4) ((float4*)dst)[i] = ((const float4*)src)[i];
}

// ---------------- edge scatter: m[dst] += t[src] * ew   (edge_index is int32) ----------------
__global__ void scatter_kernel(const int* __restrict__ ei, const float* __restrict__ ew,
                               const float* __restrict__ t, float* __restrict__ m, int E) {
    long long idx = (long long)blockIdx.x * blockDim.x + threadIdx.x;
    int e = (int)(idx >> 5);
    if (e >= E) return;
    int lane = (int)(idx & 31);
    int s = ei[e];
    int d = ei[(size_t)E + e];
    float w = ew[e];
    float4 v = *(const float4*)(t + (size_t)s * D + lane * 4);
    float4 r;
    r.x = v.x * w; r.y = v.y * w; r.z = v.z * w; r.w = v.w * w;
    float* p = m + (size_t)d * D + lane * 4;
    asm volatile("red.global.add.v4.f32 [%0], {%1,%2,%3,%4};"
                 :: "l"(p), "f"(r.x), "f"(r.y), "f"(r.z), "f"(r.w) : "memory");
}

// ---------------- head: attention gate + scale ----------------
__global__ void att_kernel(const float* __restrict__ h, const float* __restrict__ Wag,
                           const float* __restrict__ bag, float* __restrict__ out, int N) {
    long long idx = (long long)blockIdx.x * blockDim.x + threadIdx.x;
    int node = (int)(idx >> 5);
    if (node >= N) return;
    int lane = (int)(idx & 31);
    float4 hv = *(const float4*)(h + (size_t)node * D + lane * 4);
    float4 wv = *(const float4*)(Wag + lane * 4);
    float s = hv.x * wv.x + hv.y * wv.y + hv.z * wv.z + hv.w * wv.w;
#pragma unroll
    for (int o = 16; o > 0; o >>= 1) s += __shfl_xor_sync(0xFFFFFFFF, s, o);
    float att = sigf(s + bag[0]);
    float4 r;
    r.x = hv.x * att; r.y = hv.y * att; r.z = hv.z * att; r.w = hv.w * att;
    *(float4*)(out + (size_t)node * D + lane * 4) = r;
}

// ---------------- pooling (batch is int32) ----------------
__global__ void zero_pool_kernel(float* pmax, float* psum, float* cnt) {
    int i = blockIdx.x * blockDim.x + threadIdx.x;
    if (i < NGRAPH * D) { pmax[i] = 0.f; psum[i] = 0.f; }
    if (i < NGRAPH) cnt[i] = 0.f;
}

__global__ void pool_kernel(const float* __restrict__ h2, const int* __restrict__ batch,
                            float* __restrict__ pmax, float* __restrict__ psum,
                            float* __restrict__ cnt, int N) {
    long long idx = (long long)blockIdx.x * blockDim.x + threadIdx.x;
    int node = (int)(idx >> 5);
    if (node >= N) return;
    int lane = (int)(idx & 31);
    int g = batch[node];
    float4 v = *(const float4*)(h2 + (size_t)node * D + lane * 4);
    int* pm = (int*)(pmax + (size_t)g * D + lane * 4);
    atomicMax(pm + 0, __float_as_int(v.x));   // h2 >= 0 so int order == float order
    atomicMax(pm + 1, __float_as_int(v.y));
    atomicMax(pm + 2, __float_as_int(v.z));
    atomicMax(pm + 3, __float_as_int(v.w));
    float* ps = psum + (size_t)g * D + lane * 4;
    asm volatile("red.global.add.v4.f32 [%0], {%1,%2,%3,%4};"
                 :: "l"(ps), "f"(v.x), "f"(v.y), "f"(v.z), "f"(v.w) : "memory");
    if (lane == 0) atomicAdd(cnt + g, 1.0f);
}

// ---------------- final MLP ----------------
__global__ void mlp_kernel(const float* __restrict__ pmax, const float* __restrict__ psum,
                           const float* __restrict__ cnt,
                           const float* __restrict__ W1, const float* __restrict__ b1,
                           const float* __restrict__ W2, const float* __restrict__ b2,
                           float* __restrict__ out) {
    __shared__ float xp[2 * D];
    __shared__ float hid[D];
    int g = blockIdx.x;
    int t = threadIdx.x;  // 128 threads
    float c = fmaxf(cnt[g], 1.0f);
    xp[t]     = fmaxf(pmax[(size_t)g * D + t], 0.0f);
    xp[D + t] = psum[(size_t)g * D + t] / c;
    __syncthreads();
    float acc = b1[t];
#pragma unroll 8
    for (int j = 0; j < 2 * D; j++) acc += xp[j] * W1[(size_t)j * D + t];
    hid[t] = fmaxf(acc, 0.f);
    __syncthreads();
    if (t < NCLASS) {
        float o = b2[t];
#pragma unroll 8
        for (int k = 0; k < D; k++) o += hid[k] * W2[(size_t)k * NCLASS + t];
        out[(size_t)g * NCLASS + t] = o;
    }
}

// ---------------- host orchestration ----------------
extern "C" void kernel_launch(void* const* d_in, const int* in_sizes, int n_in,
                              void* d_out, int out_size) {
    const float* x     = (const float*)d_in[0];
    const int*   ei    = (const int*)d_in[1];    // int32 (jax x64 disabled)
    const int*   batch = (const int*)d_in[2];    // int32
    const float* ew    = (const float*)d_in[3];
    const float* Wa    = (const float*)d_in[4];
    const float *Wzm = (const float*)d_in[5],  *bzm = (const float*)d_in[6];
    const float *Wzs = (const float*)d_in[7],  *bzs = (const float*)d_in[8];
    const float *Wrm = (const float*)d_in[9],  *brm = (const float*)d_in[10];
    const float *Wrs = (const float*)d_in[11], *brs = (const float*)d_in[12];
    const float *Whm = (const float*)d_in[13], *bhm = (const float*)d_in[14];
    const float *Whs = (const float*)d_in[15], *bhs = (const float*)d_in[16];
    const float *Whg = (const float*)d_in[17], *bhg = (const float*)d_in[18];
    const float *Whl = (const float*)d_in[19], *bhl = (const float*)d_in[20];
    const float *bias_z = (const float*)d_in[21];
    const float *bias_r = (const float*)d_in[22];
    const float *bias_h = (const float*)d_in[23];
    const float *Wag = (const float*)d_in[24], *bag = (const float*)d_in[25];
    const float *Wae = (const float*)d_in[26], *bae = (const float*)d_in[27];
    const float *W1  = (const float*)d_in[28], *b1  = (const float*)d_in[29];
    const float *W2  = (const float*)d_in[30], *b2  = (const float*)d_in[31];
    float* out = (float*)d_out;

    const int N = in_sizes[0] / D;
    const int E = in_sizes[3];

    float *h, *t, *m, *z, *r, *ci, *gg, *cb, *pmax, *psum, *cnt;
    cudaGetSymbolAddress((void**)&h,  g_h);
    cudaGetSymbolAddress((void**)&t,  g_t);
    cudaGetSymbolAddress((void**)&m,  g_m);
    cudaGetSymbolAddress((void**)&z,  g_z);
    cudaGetSymbolAddress((void**)&r,  g_r);
    cudaGetSymbolAddress((void**)&ci, g_ci);
    cudaGetSymbolAddress((void**)&gg, g_g);
    cudaGetSymbolAddress((void**)&cb, g_cb);
    cudaGetSymbolAddress((void**)&pmax, g_pmax);
    cudaGetSymbolAddress((void**)&psum, g_psum);
    cudaGetSymbolAddress((void**)&cnt,  g_cnt);

    cudaFuncSetAttribute(gemm_fused<1>, cudaFuncAttributeMaxDynamicSharedMemorySize, GEMM_SMEM_BYTES);
    cudaFuncSetAttribute(gemm_fused<2>, cudaFuncAttributeMaxDynamicSharedMemorySize, GEMM_SMEM_BYTES);
    cudaFuncSetAttribute(gemm_fused<3>, cudaFuncAttributeMaxDynamicSharedMemorySize, GEMM_SMEM_BYTES);

    const float* cbz = cb;
    const float* cbr = cb + D;
    const float* cbh = cb + 2 * D;

    const int ND = N * D;
    const int n4 = ND / 4;
    const dim3 gg64((N + 63) / 64);

    combine_bias_kernel<<<1, D>>>(bzm, bzs, bias_z, brm, brs, bias_r, bhm, bhs, bias_h, cb);
    copy_kernel<<<(n4 + 255) / 256, 256>>>(x, h, n4);

    for (int layer = 0; layer < 3; layer++) {
        // K1 (A=h): t = h@Wa ; zp = h@Wzs + cbz ; rp = h@Wrs + cbr
        {
            GemmParams p{};
            p.o[0] = { Wa,  nullptr, nullptr, nullptr, t, 0 };
            p.o[1] = { Wzs, cbz,     nullptr, nullptr, z, 0 };
            p.o[2] = { Wrs, cbr,     nullptr, nullptr, r, 0 };
            gemm_fused<3><<<gg64, 256, GEMM_SMEM_BYTES>>>(h, p, N);
        }
        // m = t (self loops), then m[dst] += t[src]*ew
        copy_kernel<<<(n4 + 255) / 256, 256>>>(t, m, n4);
        {
            long long work = (long long)E * 32;
            scatter_kernel<<<(unsigned)((work + 255) / 256), 256>>>(ei, ew, t, m, E);
        }
        // K2 (A=m): z = sig(m@Wzm + zp) ; rh = sig(m@Wrm + rp)*h ; ci = m@Whm + cbh
        {
            GemmParams p{};
            p.o[0] = { Wzm, nullptr, z, nullptr, z,  1 };
            p.o[1] = { Wrm, nullptr, r, h,       r,  2 };
            p.o[2] = { Whm, cbh,     nullptr, nullptr, ci, 0 };
            gemm_fused<3><<<gg64, 256, GEMM_SMEM_BYTES>>>(m, p, N);
        }
        // K3 (A=rh): ci += rh@Whs
        {
            GemmParams p{};
            p.o[0] = { Whs, nullptr, nullptr, nullptr, ci, 3 };
            gemm_fused<1><<<gg64, 256, GEMM_SMEM_BYTES>>>(r, p, N);
        }
        // K4 (A=ci): g1 = ci@Whl + bhl ; h = z*(g1*sig(ci@Whg + bhg)) + (1-z)*h
        {
            GemmParams p{};
            p.o[0] = { Whl, bhl, nullptr, nullptr, gg, 0 };
            p.o[1] = { Whg, bhg, gg,      z,       h,  4 };
            gemm_fused<2><<<gg64, 256, GEMM_SMEM_BYTES>>>(ci, p, N);
        }
    }

    // attention gate: t = h * sigmoid(h @ Wag + bag)
    {
        long long work = (long long)N * 32;
        att_kernel<<<(unsigned)((work + 255) / 256), 256>>>(h, Wag, bag, t, N);
    }
    // m = relu(t @ Wae + bae)
    {
        GemmParams p{};
        p.o[0] = { Wae, bae, nullptr, nullptr, m, 5 };
        gemm_fused<1><<<gg64, 256, GEMM_SMEM_BYTES>>>(t, p, N);
    }

    // pooling + MLP head
    zero_pool_kernel<<<(NGRAPH * D + 255) / 256, 256>>>(pmax, psum, cnt);
    {
        long long work = (long long)N * 32;
        pool_kernel<<<(unsigned)((work + 255) / 256), 256>>>(m, batch, pmax, psum, cnt, N);
    }
    mlp_kernel<<<NGRAPH, D>>>(pmax, psum, cnt, W1, b1, W2, b2, out);
}

// round 16
// speedup vs baseline: 1.0219x; 1.0219x over previous
#include <cuda_runtime.h>
#include <cstdint>

#define D 128
#define NN_MAX 50000
#define NGRAPH 64
#define NCLASS 16

// ---------------- device scratch (allocation-free) ----------------
__device__ __align__(256) float g_h [NN_MAX * D];
__device__ __align__(256) float g_t [NN_MAX * D];
__device__ __align__(256) float g_m [NN_MAX * D];
__device__ __align__(256) float g_z [NN_MAX * D];
__device__ __align__(256) float g_r [NN_MAX * D];
__device__ __align__(256) float g_ci[NN_MAX * D];
__device__ __align__(256) float g_g [NN_MAX * D];
__device__ __align__(256) float g_cb[3 * D];     // combined biases: z, r, h
__device__ __align__(256) float g_pmax[NGRAPH * D];
__device__ __align__(256) float g_psum[NGRAPH * D];
__device__ __align__(256) float g_cnt [NGRAPH];

__device__ __forceinline__ float sigf(float x) { return 1.0f / (1.0f + __expf(-x)); }

__device__ __forceinline__ uint32_t to_tf32(float f) {
    uint32_t u;
    asm("cvt.rna.tf32.f32 %0, %1;" : "=r"(u) : "f"(f));
    return u;
}

__device__ __forceinline__ void cp16(void* smem_ptr, const void* gptr) {
    uint32_t s = (uint32_t)__cvta_generic_to_shared(smem_ptr);
    asm volatile("cp.async.cg.shared.global [%0], [%1], 16;" :: "r"(s), "l"(gptr));
}

// ---------------- fused multi-output TF32 tensor-core GEMM ----------------
// M=64 tiles; full-K A staged once; W via 2-stage cp.async pipeline + in-smem cvt.rna.
// modes: 0: out = acc (+bias)   1: out = sigmoid(acc + aux1[idx])
//        2: r = sigmoid(acc+aux1[idx]); out = r*aux2[idx]
//        3: out[idx] += acc     4: g2 = acc+bias[col]; out = aux2*(aux1*sigf(g2)) + (1-aux2)*out
//        5: out = relu(acc + bias)
struct GemmOut {
    const float* W;
    const float* bias;
    const float* aux1;
    const float* aux2;
    float* out;
    int mode;
};
struct GemmParams { GemmOut o[3]; };

__device__ __forceinline__ void epi_apply(const GemmOut& o, size_t idx, int col, float v) {
    switch (o.mode) {
    case 0: if (o.bias) v += o.bias[col]; o.out[idx] = v; break;
    case 1: o.out[idx] = sigf(v + o.aux1[idx]); break;
    case 2: { float r = sigf(v + o.aux1[idx]); o.out[idx] = r * o.aux2[idx]; } break;
    case 3: o.out[idx] += v; break;
    case 4: { float g2 = v + o.bias[col]; float g1 = o.aux1[idx]; float zz = o.aux2[idx];
              o.out[idx] = zz * (g1 * sigf(g2)) + (1.f - zz) * o.out[idx]; } break;
    case 5: v += o.bias[col]; o.out[idx] = fmaxf(v, 0.f); break;
    }
}

#define MMA_TF32(c, a, b) \
    asm volatile("mma.sync.aligned.m16n8k8.row.col.f32.tf32.tf32.f32 " \
        "{%0,%1,%2,%3}, {%4,%5,%6,%7}, {%8,%9}, {%0,%1,%2,%3};" \
        : "+f"((c)[0]), "+f"((c)[1]), "+f"((c)[2]), "+f"((c)[3]) \
        : "r"((a)[0]), "r"((a)[1]), "r"((a)[2]), "r"((a)[3]), "r"((b)[0]), "r"((b)[1]))

#define AS_STRIDE 132
#define BS_STRIDE 132
#define AS_WORDS (64 * AS_STRIDE)
#define BS_WORDS (32 * BS_STRIDE)
#define GEMM_SMEM_BYTES ((AS_WORDS + 2 * BS_WORDS) * 4)   // 67,584 bytes

template<int NOUT>
__global__ void __launch_bounds__(256) gemm_fused(const float* __restrict__ A, GemmParams p, int N)
{
    extern __shared__ uint32_t smem[];
    uint32_t (*As)[AS_STRIDE]  = (uint32_t (*)[AS_STRIDE])smem;                       // [64][132] full-K
    uint32_t (*Bs0)[BS_STRIDE] = (uint32_t (*)[BS_STRIDE])(smem + AS_WORDS);          // [32][132]
    uint32_t (*Bs1)[BS_STRIDE] = (uint32_t (*)[BS_STRIDE])(smem + AS_WORDS + BS_WORDS);

    const int tid  = threadIdx.x;
    const int lane = tid & 31;
    const int wid  = tid >> 5;
    const int wm   = wid >> 2;          // 0..1 -> m offset wm*32
    const int wn   = wid & 3;           // 0..3 -> n offset wn*32
    const int row0 = blockIdx.x * 64;
    const int gid  = lane >> 2;         // groupID 0..7
    const int tig  = lane & 3;          // thread-in-group 0..3

    // W staging coords: 1024 float4 per chunk, 4 per thread
    const int bk = tid >> 5, bng = (tid & 31) * 4;   // k = bk + i*8, col bng

    // ---- stage full-K A once per CTA: 64 rows x 128 cols = 2048 float4, 8 per thread ----
#pragma unroll
    for (int i = 0; i < 8; i++) {
        int f = tid + i * 256;              // 0..2047
        int r = f >> 5, kg = (f & 31) * 4;  // r 0..63, kg 0..124
        int grow = row0 + r;
        float4 v = make_float4(0.f, 0.f, 0.f, 0.f);
        if (grow < N) v = *(const float4*)&A[(size_t)grow * D + kg];
        As[r][kg + 0] = to_tf32(v.x); As[r][kg + 1] = to_tf32(v.y);
        As[r][kg + 2] = to_tf32(v.z); As[r][kg + 3] = to_tf32(v.w);
    }

    for (int o = 0; o < NOUT; o++) {
        const float* __restrict__ W = p.o[o].W;
        float acc[2][4][4];             // [mfrag][nfrag][reg]
#pragma unroll
        for (int mf = 0; mf < 2; mf++)
#pragma unroll
            for (int nf = 0; nf < 4; nf++)
#pragma unroll
                for (int q = 0; q < 4; q++) acc[mf][nf][q] = 0.f;

        // prologue: async-load W chunk 0 into buf0 (raw f32 bits)
#pragma unroll
        for (int i = 0; i < 4; i++) {
            int k = bk + i * 8;
            cp16(&Bs0[k][bng], &W[(size_t)k * D + bng]);
        }
        asm volatile("cp.async.commit_group;");

#pragma unroll
        for (int kcs = 0; kcs < 4; kcs++) {
            uint32_t (*Bsb)[BS_STRIDE] = (kcs & 1) ? Bs1 : Bs0;
            // wait for current chunk to land
            asm volatile("cp.async.wait_group 0;");
            __syncthreads();
            // in-smem cvt.rna (f32 bits -> tf32), 4 float4 per thread
#pragma unroll
            for (int i = 0; i < 4; i++) {
                int f = tid + i * 256;              // 0..1023
                int r = f >> 5, c4 = (f & 31) * 4;
                uint32_t* wp = &Bsb[r][c4];
                uint4 v = *(uint4*)wp;
                wp[0] = to_tf32(__uint_as_float(v.x));
                wp[1] = to_tf32(__uint_as_float(v.y));
                wp[2] = to_tf32(__uint_as_float(v.z));
                wp[3] = to_tf32(__uint_as_float(v.w));
            }
            __syncthreads();
            // issue next chunk into other buffer (overlaps compute below)
            if (kcs + 1 < 4) {
                const int kc = (kcs + 1) * 32;
                uint32_t (*Bsn)[BS_STRIDE] = (kcs & 1) ? Bs0 : Bs1;
#pragma unroll
                for (int i = 0; i < 4; i++) {
                    int k = bk + i * 8;
                    cp16(&Bsn[k][bng], &W[(size_t)(kc + k) * D + bng]);
                }
                asm volatile("cp.async.commit_group;");
            }
            // compute on current chunk
            const int kofs = kcs * 32;
#pragma unroll
            for (int k8 = 0; k8 < 4; k8++) {
                const int kb = kofs + k8 * 8;
                uint32_t af[2][4];
#pragma unroll
                for (int mf = 0; mf < 2; mf++) {
                    int r = wm * 32 + mf * 16 + gid;
                    af[mf][0] = As[r][kb + tig];
                    af[mf][1] = As[r + 8][kb + tig];
                    af[mf][2] = As[r][kb + tig + 4];
                    af[mf][3] = As[r + 8][kb + tig + 4];
                }
                uint32_t bf[4][2];
#pragma unroll
                for (int nf = 0; nf < 4; nf++) {
                    int n = wn * 32 + nf * 8 + gid;
                    bf[nf][0] = Bsb[k8 * 8 + tig][n];
                    bf[nf][1] = Bsb[k8 * 8 + tig + 4][n];
                }
#pragma unroll
                for (int mf = 0; mf < 2; mf++)
#pragma unroll
                    for (int nf = 0; nf < 4; nf++)
                        MMA_TF32(acc[mf][nf], af[mf], bf[nf]);
            }
        }
        __syncthreads();   // all reads of Bs done before next output's prologue overwrites

        // epilogue
        const GemmOut& po = p.o[o];
#pragma unroll
        for (int mf = 0; mf < 2; mf++) {
            int ra = row0 + wm * 32 + mf * 16 + gid;
            int rb = ra + 8;
#pragma unroll
            for (int nf = 0; nf < 4; nf++) {
                int c0 = wn * 32 + nf * 8 + tig * 2;
                if (ra < N) {
                    epi_apply(po, (size_t)ra * D + c0,     c0,     acc[mf][nf][0]);
                    epi_apply(po, (size_t)ra * D + c0 + 1, c0 + 1, acc[mf][nf][1]);
                }
                if (rb < N) {
                    epi_apply(po, (size_t)rb * D + c0,     c0,     acc[mf][nf][2]);
                    epi_apply(po, (size_t)rb * D + c0 + 1, c0 + 1, acc[mf][nf][3]);
                }
            }
        }
    }
}

// ---------------- small kernels ----------------
__global__ void combine_bias_kernel(
    const float* bzm, const float* bzs, const float* bias_z,
    const float* brm, const float* brs, const float* bias_r,
    const float* bhm, const float* bhs, const float* bias_h, float* cb) {
    int i = threadIdx.x;
    cb[i]         = bzm[i] + bzs[i] + bias_z[i];
    cb[D + i]     = brm[i] + brs[i] + bias_r[i];
    cb[2 * D + i] = bhm[i] + bhs[i] + bias_h[i];
}

__global__ void copy_kernel(const float* __restrict__ src, float* __restrict__ dst, int n4) {
    int i = blockIdx.x * blockDim.x + threadIdx.x;
    if (i < n4) ((float4*)dst)[i] = ((const float4*)src)[i];
}

// ---------------- edge scatter: m[dst] += t[src] * ew   (edge_index is int32) ----------------
__global__ void scatter_kernel(const int* __restrict__ ei, const float* __restrict__ ew,
                               const float* __restrict__ t, float* __restrict__ m, int E) {
    long long idx = (long long)blockIdx.x * blockDim.x + threadIdx.x;
    int e = (int)(idx >> 5);
    if (e >= E) return;
    int lane = (int)(idx & 31);
    int s = ei[e];
    int d = ei[(size_t)E + e];
    float w = ew[e];
    float4 v = *(const float4*)(t + (size_t)s * D + lane * 4);
    float4 r;
    r.x = v.x * w; r.y = v.y * w; r.z = v.z * w; r.w = v.w * w;
    float* p = m + (size_t)d * D + lane * 4;
    asm volatile("red.global.add.v4.f32 [%0], {%1,%2,%3,%4};"
                 :: "l"(p), "f"(r.x), "f"(r.y), "f"(r.z), "f"(r.w) : "memory");
}

// ---------------- head: attention gate + scale ----------------
__global__ void att_kernel(const float* __restrict__ h, const float* __restrict__ Wag,
                           const float* __restrict__ bag, float* __restrict__ out, int N) {
    long long idx = (long long)blockIdx.x * blockDim.x + threadIdx.x;
    int node = (int)(idx >> 5);
    if (node >= N) return;
    int lane = (int)(idx & 31);
    float4 hv = *(const float4*)(h + (size_t)node * D + lane * 4);
    float4 wv = *(const float4*)(Wag + lane * 4);
    float s = hv.x * wv.x + hv.y * wv.y + hv.z * wv.z + hv.w * wv.w;
#pragma unroll
    for (int o = 16; o > 0; o >>= 1) s += __shfl_xor_sync(0xFFFFFFFF, s, o);
    float att = sigf(s + bag[0]);
    float4 r;
    r.x = hv.x * att; r.y = hv.y * att; r.z = hv.z * att; r.w = hv.w * att;
    *(float4*)(out + (size_t)node * D + lane * 4) = r;
}

// ---------------- pooling (batch is int32) ----------------
__global__ void zero_pool_kernel(float* pmax, float* psum, float* cnt) {
    int i = blockIdx.x * blockDim.x + threadIdx.x;
    if (i < NGRAPH * D) { pmax[i] = 0.f; psum[i] = 0.f; }
    if (i < NGRAPH) cnt[i] = 0.f;
}

__global__ void pool_kernel(const float* __restrict__ h2, const int* __restrict__ batch,
                            float* __restrict__ pmax, float* __restrict__ psum,
                            float* __restrict__ cnt, int N) {
    long long idx = (long long)blockIdx.x * blockDim.x + threadIdx.x;
    int node = (int)(idx >> 5);
    if (node >= N) return;
    int lane = (int)(idx & 31);
    int g = batch[node];
    float4 v = *(const float4*)(h2 + (size_t)node * D + lane * 4);
    int* pm = (int*)(pmax + (size_t)g * D + lane * 4);
    atomicMax(pm + 0, __float_as_int(v.x));   // h2 >= 0 so int order == float order
    atomicMax(pm + 1, __float_as_int(v.y));
    atomicMax(pm + 2, __float_as_int(v.z));
    atomicMax(pm + 3, __float_as_int(v.w));
    float* ps = psum + (size_t)g * D + lane * 4;
    asm volatile("red.global.add.v4.f32 [%0], {%1,%2,%3,%4};"
                 :: "l"(ps), "f"(v.x), "f"(v.y), "f"(v.z), "f"(v.w) : "memory");
    if (lane == 0) atomicAdd(cnt + g, 1.0f);
}

// ---------------- final MLP ----------------
__global__ void mlp_kernel(const float* __restrict__ pmax, const float* __restrict__ psum,
                           const float* __restrict__ cnt,
                           const float* __restrict__ W1, const float* __restrict__ b1,
                           const float* __restrict__ W2, const float* __restrict__ b2,
                           float* __restrict__ out) {
    __shared__ float xp[2 * D];
    __shared__ float hid[D];
    int g = blockIdx.x;
    int t = threadIdx.x;  // 128 threads
    float c = fmaxf(cnt[g], 1.0f);
    xp[t]     = fmaxf(pmax[(size_t)g * D + t], 0.0f);
    xp[D + t] = psum[(size_t)g * D + t] / c;
    __syncthreads();
    float acc = b1[t];
#pragma unroll 8
    for (int j = 0; j < 2 * D; j++) acc += xp[j] * W1[(size_t)j * D + t];
    hid[t] = fmaxf(acc, 0.f);
    __syncthreads();
    if (t < NCLASS) {
        float o = b2[t];
#pragma unroll 8
        for (int k = 0; k < D; k++) o += hid[k] * W2[(size_t)k * NCLASS + t];
        out[(size_t)g * NCLASS + t] = o;
    }
}

// ---------------- host orchestration ----------------
extern "C" void kernel_launch(void* const* d_in, const int* in_sizes, int n_in,
                              void* d_out, int out_size) {
    const float* x     = (const float*)d_in[0];
    const int*   ei    = (const int*)d_in[1];    // int32 (jax x64 disabled)
    const int*   batch = (const int*)d_in[2];    // int32
    const float* ew    = (const float*)d_in[3];
    const float* Wa    = (const float*)d_in[4];
    const float *Wzm = (const float*)d_in[5],  *bzm = (const float*)d_in[6];
    const float *Wzs = (const float*)d_in[7],  *bzs = (const float*)d_in[8];
    const float *Wrm = (const float*)d_in[9],  *brm = (const float*)d_in[10];
    const float *Wrs = (const float*)d_in[11], *brs = (const float*)d_in[12];
    const float *Whm = (const float*)d_in[13], *bhm = (const float*)d_in[14];
    const float *Whs = (const float*)d_in[15], *bhs = (const float*)d_in[16];
    const float *Whg = (const float*)d_in[17], *bhg = (const float*)d_in[18];
    const float *Whl = (const float*)d_in[19], *bhl = (const float*)d_in[20];
    const float *bias_z = (const float*)d_in[21];
    const float *bias_r = (const float*)d_in[22];
    const float *bias_h = (const float*)d_in[23];
    const float *Wag = (const float*)d_in[24], *bag = (const float*)d_in[25];
    const float *Wae = (const float*)d_in[26], *bae = (const float*)d_in[27];
    const float *W1  = (const float*)d_in[28], *b1  = (const float*)d_in[29];
    const float *W2  = (const float*)d_in[30], *b2  = (const float*)d_in[31];
    float* out = (float*)d_out;

    const int N = in_sizes[0] / D;
    const int E = in_sizes[3];

    float *h, *t, *m, *z, *r, *ci, *gg, *cb, *pmax, *psum, *cnt;
    cudaGetSymbolAddress((void**)&h,  g_h);
    cudaGetSymbolAddress((void**)&t,  g_t);
    cudaGetSymbolAddress((void**)&m,  g_m);
    cudaGetSymbolAddress((void**)&z,  g_z);
    cudaGetSymbolAddress((void**)&r,  g_r);
    cudaGetSymbolAddress((void**)&ci, g_ci);
    cudaGetSymbolAddress((void**)&gg, g_g);
    cudaGetSymbolAddress((void**)&cb, g_cb);
    cudaGetSymbolAddress((void**)&pmax, g_pmax);
    cudaGetSymbolAddress((void**)&psum, g_psum);
    cudaGetSymbolAddress((void**)&cnt,  g_cnt);

    cudaFuncSetAttribute(gemm_fused<1>, cudaFuncAttributeMaxDynamicSharedMemorySize, GEMM_SMEM_BYTES);
    cudaFuncSetAttribute(gemm_fused<2>, cudaFuncAttributeMaxDynamicSharedMemorySize, GEMM_SMEM_BYTES);
    cudaFuncSetAttribute(gemm_fused<3>, cudaFuncAttributeMaxDynamicSharedMemorySize, GEMM_SMEM_BYTES);

    const float* cbz = cb;
    const float* cbr = cb + D;
    const float* cbh = cb + 2 * D;

    const int ND = N * D;
    const int n4 = ND / 4;
    const dim3 gg64((N + 63) / 64);

    combine_bias_kernel<<<1, D>>>(bzm, bzs, bias_z, brm, brs, bias_r, bhm, bhs, bias_h, cb);
    copy_kernel<<<(n4 + 255) / 256, 256>>>(x, h, n4);

    for (int layer = 0; layer < 3; layer++) {
        // K1 (A=h): t = h@Wa ; zp = h@Wzs + cbz ; rp = h@Wrs + cbr
        {
            GemmParams p{};
            p.o[0] = { Wa,  nullptr, nullptr, nullptr, t, 0 };
            p.o[1] = { Wzs, cbz,     nullptr, nullptr, z, 0 };
            p.o[2] = { Wrs, cbr,     nullptr, nullptr, r, 0 };
            gemm_fused<3><<<gg64, 256, GEMM_SMEM_BYTES>>>(h, p, N);
        }
        // m = t (self loops), then m[dst] += t[src]*ew
        copy_kernel<<<(n4 + 255) / 256, 256>>>(t, m, n4);
        {
            long long work = (long long)E * 32;
            scatter_kernel<<<(unsigned)((work + 255) / 256), 256>>>(ei, ew, t, m, E);
        }
        // K2 (A=m): z = sig(m@Wzm + zp) ; rh = sig(m@Wrm + rp)*h ; ci = m@Whm + cbh
        {
            GemmParams p{};
            p.o[0] = { Wzm, nullptr, z, nullptr, z,  1 };
            p.o[1] = { Wrm, nullptr, r, h,       r,  2 };
            p.o[2] = { Whm, cbh,     nullptr, nullptr, ci, 0 };
            gemm_fused<3><<<gg64, 256, GEMM_SMEM_BYTES>>>(m, p, N);
        }
        // K3 (A=rh): ci += rh@Whs
        {
            GemmParams p{};
            p.o[0] = { Whs, nullptr, nullptr, nullptr, ci, 3 };
            gemm_fused<1><<<gg64, 256, GEMM_SMEM_BYTES>>>(r, p, N);
        }
        // K4 (A=ci): g1 = ci@Whl + bhl ; h = z*(g1*sig(ci@Whg + bhg)) + (1-z)*h
        {
            GemmParams p{};
            p.o[0] = { Whl, bhl, nullptr, nullptr, gg, 0 };
            p.o[1] = { Whg, bhg, gg,      z,       h,  4 };
            gemm_fused<2><<<gg64, 256, GEMM_SMEM_BYTES>>>(ci, p, N);
        }
    }

    // attention gate: t = h * sigmoid(h @ Wag + bag)
    {
        long long work = (long long)N * 32;
        att_kernel<<<(unsigned)((work + 255) / 256), 256>>>(h, Wag, bag, t, N);
    }
    // m = relu(t @ Wae + bae)
    {
        GemmParams p{};
        p.o[0] = { Wae, bae, nullptr, nullptr, m, 5 };
        gemm_fused<1><<<gg64, 256, GEMM_SMEM_BYTES>>>(t, p, N);
    }

    // pooling + MLP head
    zero_pool_kernel<<<(NGRAPH * D + 255) / 256, 256>>>(pmax, psum, cnt);
    {
        long long work = (long long)N * 32;
        pool_kernel<<<(unsigned)((work + 255) / 256), 256>>>(m, batch, pmax, psum, cnt, N);
    }
    mlp_kernel<<<NGRAPH, D>>>(pmax, psum, cnt, W1, b1, W2, b2, out);
}

// round 17
// speedup vs baseline: 1.0916x; 1.0682x over previous
#include <cuda_runtime.h>
#include <cstdint>

#define D 128
#define NN_MAX 50000
#define NGRAPH 64
#define NCLASS 16

// ---------------- device scratch (allocation-free) ----------------
__device__ __align__(256) float g_h [NN_MAX * D];
__device__ __align__(256) float g_t [NN_MAX * D];
__device__ __align__(256) float g_m [NN_MAX * D];
__device__ __align__(256) float g_z [NN_MAX * D];
__device__ __align__(256) float g_r [NN_MAX * D];
__device__ __align__(256) float g_ci[NN_MAX * D];
__device__ __align__(256) float g_g [NN_MAX * D];
__device__ __align__(256) float g_cb[3 * D];     // combined biases: z, r, h
__device__ __align__(256) float g_pmax[NGRAPH * D];
__device__ __align__(256) float g_psum[NGRAPH * D];
__device__ __align__(256) float g_cnt [NGRAPH];

__device__ __forceinline__ float sigf(float x) { return 1.0f / (1.0f + __expf(-x)); }

__device__ __forceinline__ uint32_t to_tf32(float f) {
    uint32_t u;
    asm("cvt.rna.tf32.f32 %0, %1;" : "=r"(u) : "f"(f));
    return u;
}

// ---------------- fused multi-output TF32 tensor-core GEMM (R14 core) ----------------
// M=64 tiles; full-K A staged ONCE per CTA; W chunks (32 k-rows) staged per output.
// modes: 0: out = acc (+bias)   1: out = sigmoid(acc + aux1[idx])
//        2: r = sigmoid(acc+aux1[idx]); out = r*aux2[idx]
//        3: out[idx] += acc     4: g2 = acc+bias[col]; out = aux2*(aux1*sigf(g2)) + (1-aux2)*out
//        5: out = relu(acc + bias)   6: out = acc, also write to aux2 (second dest)
struct GemmOut {
    const float* W;
    const float* bias;
    const float* aux1;
    const float* aux2;
    float* out;
    int mode;
};
struct GemmParams { GemmOut o[3]; };

__device__ __forceinline__ void epi_apply(const GemmOut& o, size_t idx, int col, float v) {
    switch (o.mode) {
    case 0: if (o.bias) v += o.bias[col]; o.out[idx] = v; break;
    case 1: o.out[idx] = sigf(v + o.aux1[idx]); break;
    case 2: { float r = sigf(v + o.aux1[idx]); o.out[idx] = r * o.aux2[idx]; } break;
    case 3: o.out[idx] += v; break;
    case 4: { float g2 = v + o.bias[col]; float g1 = o.aux1[idx]; float zz = o.aux2[idx];
              o.out[idx] = zz * (g1 * sigf(g2)) + (1.f - zz) * o.out[idx]; } break;
    case 5: v += o.bias[col]; o.out[idx] = fmaxf(v, 0.f); break;
    case 6: o.out[idx] = v; ((float*)o.aux2)[idx] = v; break;
    }
}

#define MMA_TF32(c, a, b) \
    asm volatile("mma.sync.aligned.m16n8k8.row.col.f32.tf32.tf32.f32 " \
        "{%0,%1,%2,%3}, {%4,%5,%6,%7}, {%8,%9}, {%0,%1,%2,%3};" \
        : "+f"((c)[0]), "+f"((c)[1]), "+f"((c)[2]), "+f"((c)[3]) \
        : "r"((a)[0]), "r"((a)[1]), "r"((a)[2]), "r"((a)[3]), "r"((b)[0]), "r"((b)[1]))

#define AS_STRIDE 132
#define BS_STRIDE 132
#define AS_WORDS (64 * AS_STRIDE)
#define BS_WORDS (32 * BS_STRIDE)
#define GEMM_SMEM_BYTES ((AS_WORDS + BS_WORDS) * 4)   // 50,688 bytes

template<int NOUT>
__global__ void __launch_bounds__(256) gemm_fused(const float* __restrict__ A, GemmParams p, int N)
{
    extern __shared__ uint32_t smem[];
    uint32_t (*As)[AS_STRIDE] = (uint32_t (*)[AS_STRIDE])smem;             // [64][132] full-K
    uint32_t (*Bs)[BS_STRIDE] = (uint32_t (*)[BS_STRIDE])(smem + AS_WORDS);// [32][132]

    const int tid  = threadIdx.x;
    const int lane = tid & 31;
    const int wid  = tid >> 5;
    const int wm   = wid >> 2;          // 0..1 -> m offset wm*32
    const int wn   = wid & 3;           // 0..3 -> n offset wn*32
    const int row0 = blockIdx.x * 64;
    const int gid  = lane >> 2;         // groupID 0..7
    const int tig  = lane & 3;          // thread-in-group 0..3

    // ---- stage full-K A once per CTA: 64 rows x 128 cols = 2048 float4, 8 per thread ----
#pragma unroll
    for (int i = 0; i < 8; i++) {
        int f = tid + i * 256;              // 0..2047
        int r = f >> 5, kg = (f & 31) * 4;  // r 0..63, kg 0..124
        int grow = row0 + r;
        float4 v = make_float4(0.f, 0.f, 0.f, 0.f);
        if (grow < N) v = *(const float4*)&A[(size_t)grow * D + kg];
        As[r][kg + 0] = to_tf32(v.x); As[r][kg + 1] = to_tf32(v.y);
        As[r][kg + 2] = to_tf32(v.z); As[r][kg + 3] = to_tf32(v.w);
    }

    for (int o = 0; o < NOUT; o++) {
        const float* __restrict__ W = p.o[o].W;
        float acc[2][4][4];             // [mfrag][nfrag][reg]
#pragma unroll
        for (int mf = 0; mf < 2; mf++)
#pragma unroll
            for (int nf = 0; nf < 4; nf++)
#pragma unroll
                for (int q = 0; q < 4; q++) acc[mf][nf][q] = 0.f;

        for (int kc = 0; kc < D; kc += 32) {
            // W chunk: 32 k-rows x 128 n  (1024 float4; 4 per thread), k-major as-is
#pragma unroll
            for (int i = 0; i < 4; i++) {
                int f = tid + i * 256;
                int k = f >> 5, ng = (f & 31) * 4;
                float4 v = *(const float4*)&W[(size_t)(kc + k) * D + ng];
                Bs[k][ng + 0] = to_tf32(v.x); Bs[k][ng + 1] = to_tf32(v.y);
                Bs[k][ng + 2] = to_tf32(v.z); Bs[k][ng + 3] = to_tf32(v.w);
            }
            __syncthreads();

#pragma unroll
            for (int k8 = 0; k8 < 4; k8++) {
                const int kb = kc + k8 * 8;
                uint32_t af[2][4];
#pragma unroll
                for (int mf = 0; mf < 2; mf++) {
                    int r = wm * 32 + mf * 16 + gid;
                    af[mf][0] = As[r][kb + tig];
                    af[mf][1] = As[r + 8][kb + tig];
                    af[mf][2] = As[r][kb + tig + 4];
                    af[mf][3] = As[r + 8][kb + tig + 4];
                }
                uint32_t bf[4][2];
#pragma unroll
                for (int nf = 0; nf < 4; nf++) {
                    int n = wn * 32 + nf * 8 + gid;
                    bf[nf][0] = Bs[k8 * 8 + tig][n];
                    bf[nf][1] = Bs[k8 * 8 + tig + 4][n];
                }
#pragma unroll
                for (int mf = 0; mf < 2; mf++)
#pragma unroll
                    for (int nf = 0; nf < 4; nf++)
                        MMA_TF32(acc[mf][nf], af[mf], bf[nf]);
            }
            __syncthreads();
        }

        // epilogue
        const GemmOut& po = p.o[o];
#pragma unroll
        for (int mf = 0; mf < 2; mf++) {
            int ra = row0 + wm * 32 + mf * 16 + gid;
            int rb = ra + 8;
#pragma unroll
            for (int nf = 0; nf < 4; nf++) {
                int c0 = wn * 32 + nf * 8 + tig * 2;
                if (ra < N) {
                    epi_apply(po, (size_t)ra * D + c0,     c0,     acc[mf][nf][0]);
                    epi_apply(po, (size_t)ra * D + c0 + 1, c0 + 1, acc[mf][nf][1]);
                }
                if (rb < N) {
                    epi_apply(po, (size_t)rb * D + c0,     c0,     acc[mf][nf][2]);
                    epi_apply(po, (size_t)rb * D + c0 + 1, c0 + 1, acc[mf][nf][3]);
                }
            }
        }
        if (o + 1 < NOUT) __syncthreads();
    }
}

// ---------------- small kernels ----------------
__global__ void combine_bias_kernel(
    const float* bzm, const float* bzs, const float* bias_z,
    const float* brm, const float* brs, const float* bias_r,
    const float* bhm, const float* bhs, const float* bias_h, float* cb) {
    int i = threadIdx.x;
    cb[i]         = bzm[i] + bzs[i] + bias_z[i];
    cb[D + i]     = brm[i] + brs[i] + bias_r[i];
    cb[2 * D + i] = bhm[i] + bhs[i] + bias_h[i];
}

__global__ void copy_kernel(const float* __restrict__ src, float* __restrict__ dst, int n4) {
    int i = blockIdx.x * blockDim.x + threadIdx.x;
    if (i < n4) ((float4*)dst)[i] = ((const float4*)src)[i];
}

// ---------------- edge scatter: m[dst] += t[src] * ew   (edge_index is int32) ----------------
__global__ void scatter_kernel(const int* __restrict__ ei, const float* __restrict__ ew,
                               const float* __restrict__ t, float* __restrict__ m, int E) {
    long long idx = (long long)blockIdx.x * blockDim.x + threadIdx.x;
    int e = (int)(idx >> 5);
    if (e >= E) return;
    int lane = (int)(idx & 31);
    int s = ei[e];
    int d = ei[(size_t)E + e];
    float w = ew[e];
    float4 v = *(const float4*)(t + (size_t)s * D + lane * 4);
    float4 r;
    r.x = v.x * w; r.y = v.y * w; r.z = v.z * w; r.w = v.w * w;
    float* p = m + (size_t)d * D + lane * 4;
    asm volatile("red.global.add.v4.f32 [%0], {%1,%2,%3,%4};"
                 :: "l"(p), "f"(r.x), "f"(r.y), "f"(r.z), "f"(r.w) : "memory");
}

// ---------------- head: attention gate + scale ----------------
__global__ void att_kernel(const float* __restrict__ h, const float* __restrict__ Wag,
                           const float* __restrict__ bag, float* __restrict__ out, int N) {
    long long idx = (long long)blockIdx.x * blockDim.x + threadIdx.x;
    int node = (int)(idx >> 5);
    if (node >= N) return;
    int lane = (int)(idx & 31);
    float4 hv = *(const float4*)(h + (size_t)node * D + lane * 4);
    float4 wv = *(const float4*)(Wag + lane * 4);
    float s = hv.x * wv.x + hv.y * wv.y + hv.z * wv.z + hv.w * wv.w;
#pragma unroll
    for (int o = 16; o > 0; o >>= 1) s += __shfl_xor_sync(0xFFFFFFFF, s, o);
    float att = sigf(s + bag[0]);
    float4 r;
    r.x = hv.x * att; r.y = hv.y * att; r.z = hv.z * att; r.w = hv.w * att;
    *(float4*)(out + (size_t)node * D + lane * 4) = r;
}

// ---------------- pooling (batch is int32) ----------------
__global__ void zero_pool_kernel(float* pmax, float* psum, float* cnt) {
    int i = blockIdx.x * blockDim.x + threadIdx.x;
    if (i < NGRAPH * D) { pmax[i] = 0.f; psum[i] = 0.f; }
    if (i < NGRAPH) cnt[i] = 0.f;
}

__global__ void pool_kernel(const float* __restrict__ h2, const int* __restrict__ batch,
                            float* __restrict__ pmax, float* __restrict__ psum,
                            float* __restrict__ cnt, int N) {
    long long idx = (long long)blockIdx.x * blockDim.x + threadIdx.x;
    int node = (int)(idx >> 5);
    if (node >= N) return;
    int lane = (int)(idx & 31);
    int g = batch[node];
    float4 v = *(const float4*)(h2 + (size_t)node * D + lane * 4);
    int* pm = (int*)(pmax + (size_t)g * D + lane * 4);
    atomicMax(pm + 0, __float_as_int(v.x));   // h2 >= 0 so int order == float order
    atomicMax(pm + 1, __float_as_int(v.y));
    atomicMax(pm + 2, __float_as_int(v.z));
    atomicMax(pm + 3, __float_as_int(v.w));
    float* ps = psum + (size_t)g * D + lane * 4;
    asm volatile("red.global.add.v4.f32 [%0], {%1,%2,%3,%4};"
                 :: "l"(ps), "f"(v.x), "f"(v.y), "f"(v.z), "f"(v.w) : "memory");
    if (lane == 0) atomicAdd(cnt + g, 1.0f);
}

// ---------------- final MLP ----------------
__global__ void mlp_kernel(const float* __restrict__ pmax, const float* __restrict__ psum,
                           const float* __restrict__ cnt,
                           const float* __restrict__ W1, const float* __restrict__ b1,
                           const float* __restrict__ W2, const float* __restrict__ b2,
                           float* __restrict__ out) {
    __shared__ float xp[2 * D];
    __shared__ float hid[D];
    int g = blockIdx.x;
    int t = threadIdx.x;  // 128 threads
    float c = fmaxf(cnt[g], 1.0f);
    xp[t]     = fmaxf(pmax[(size_t)g * D + t], 0.0f);
    xp[D + t] = psum[(size_t)g * D + t] / c;
    __syncthreads();
    float acc = b1[t];
#pragma unroll 8
    for (int j = 0; j < 2 * D; j++) acc += xp[j] * W1[(size_t)j * D + t];
    hid[t] = fmaxf(acc, 0.f);
    __syncthreads();
    if (t < NCLASS) {
        float o = b2[t];
#pragma unroll 8
        for (int k = 0; k < D; k++) o += hid[k] * W2[(size_t)k * NCLASS + t];
        out[(size_t)g * NCLASS + t] = o;
    }
}

// ---------------- host orchestration ----------------
extern "C" void kernel_launch(void* const* d_in, const int* in_sizes, int n_in,
                              void* d_out, int out_size) {
    const float* x     = (const float*)d_in[0];
    const int*   ei    = (const int*)d_in[1];    // int32 (jax x64 disabled)
    const int*   batch = (const int*)d_in[2];    // int32
    const float* ew    = (const float*)d_in[3];
    const float* Wa    = (const float*)d_in[4];
    const float *Wzm = (const float*)d_in[5],  *bzm = (const float*)d_in[6];
    const float *Wzs = (const float*)d_in[7],  *bzs = (const float*)d_in[8];
    const float *Wrm = (const float*)d_in[9],  *brm = (const float*)d_in[10];
    const float *Wrs = (const float*)d_in[11], *brs = (const float*)d_in[12];
    const float *Whm = (const float*)d_in[13], *bhm = (const float*)d_in[14];
    const float *Whs = (const float*)d_in[15], *bhs = (const float*)d_in[16];
    const float *Whg = (const float*)d_in[17], *bhg = (const float*)d_in[18];
    const float *Whl = (const float*)d_in[19], *bhl = (const float*)d_in[20];
    const float *bias_z = (const float*)d_in[21];
    const float *bias_r = (const float*)d_in[22];
    const float *bias_h = (const float*)d_in[23];
    const float *Wag = (const float*)d_in[24], *bag = (const float*)d_in[25];
    const float *Wae = (const float*)d_in[26], *bae = (const float*)d_in[27];
    const float *W1  = (const float*)d_in[28], *b1  = (const float*)d_in[29];
    const float *W2  = (const float*)d_in[30], *b2  = (const float*)d_in[31];
    float* out = (float*)d_out;

    const int N = in_sizes[0] / D;
    const int E = in_sizes[3];

    float *h, *t, *m, *z, *r, *ci, *gg, *cb, *pmax, *psum, *cnt;
    cudaGetSymbolAddress((void**)&h,  g_h);
    cudaGetSymbolAddress((void**)&t,  g_t);
    cudaGetSymbolAddress((void**)&m,  g_m);
    cudaGetSymbolAddress((void**)&z,  g_z);
    cudaGetSymbolAddress((void**)&r,  g_r);
    cudaGetSymbolAddress((void**)&ci, g_ci);
    cudaGetSymbolAddress((void**)&gg, g_g);
    cudaGetSymbolAddress((void**)&cb, g_cb);
    cudaGetSymbolAddress((void**)&pmax, g_pmax);
    cudaGetSymbolAddress((void**)&psum, g_psum);
    cudaGetSymbolAddress((void**)&cnt,  g_cnt);

    cudaFuncSetAttribute(gemm_fused<1>, cudaFuncAttributeMaxDynamicSharedMemorySize, GEMM_SMEM_BYTES);
    cudaFuncSetAttribute(gemm_fused<2>, cudaFuncAttributeMaxDynamicSharedMemorySize, GEMM_SMEM_BYTES);
    cudaFuncSetAttribute(gemm_fused<3>, cudaFuncAttributeMaxDynamicSharedMemorySize, GEMM_SMEM_BYTES);

    const float* cbz = cb;
    const float* cbr = cb + D;
    const float* cbh = cb + 2 * D;

    const int ND = N * D;
    const int n4 = ND / 4;
    const dim3 gg64((N + 63) / 64);

    combine_bias_kernel<<<1, D>>>(bzm, bzs, bias_z, brm, brs, bias_r, bhm, bhs, bias_h, cb);
    copy_kernel<<<(n4 + 255) / 256, 256>>>(x, h, n4);

    for (int layer = 0; layer < 3; layer++) {
        // K1 (A=h): t = h@Wa (also -> m, self loops) ; zp = h@Wzs + cbz ; rp = h@Wrs + cbr
        {
            GemmParams p{};
            p.o[0] = { Wa,  nullptr, nullptr, m,       t, 6 };
            p.o[1] = { Wzs, cbz,     nullptr, nullptr, z, 0 };
            p.o[2] = { Wrs, cbr,     nullptr, nullptr, r, 0 };
            gemm_fused<3><<<gg64, 256, GEMM_SMEM_BYTES>>>(h, p, N);
        }
        // m[dst] += t[src]*ew
        {
            long long work = (long long)E * 32;
            scatter_kernel<<<(unsigned)((work + 255) / 256), 256>>>(ei, ew, t, m, E);
        }
        // K2 (A=m): z = sig(m@Wzm + zp) ; rh = sig(m@Wrm + rp)*h ; ci = m@Whm + cbh
        {
            GemmParams p{};
            p.o[0] = { Wzm, nullptr, z, nullptr, z,  1 };
            p.o[1] = { Wrm, nullptr, r, h,       r,  2 };
            p.o[2] = { Whm, cbh,     nullptr, nullptr, ci, 0 };
            gemm_fused<3><<<gg64, 256, GEMM_SMEM_BYTES>>>(m, p, N);
        }
        // K3 (A=rh): ci += rh@Whs
        {
            GemmParams p{};
            p.o[0] = { Whs, nullptr, nullptr, nullptr, ci, 3 };
            gemm_fused<1><<<gg64, 256, GEMM_SMEM_BYTES>>>(r, p, N);
        }
        // K4 (A=ci): g1 = ci@Whl + bhl ; h = z*(g1*sig(ci@Whg + bhg)) + (1-z)*h
        {
            GemmParams p{};
            p.o[0] = { Whl, bhl, nullptr, nullptr, gg, 0 };
            p.o[1] = { Whg, bhg, gg,      z,       h,  4 };
            gemm_fused<2><<<gg64, 256, GEMM_SMEM_BYTES>>>(ci, p, N);
        }
    }

    // attention gate: t = h * sigmoid(h @ Wag + bag)
    {
        long long work = (long long)N * 32;
        att_kernel<<<(unsigned)((work + 255) / 256), 256>>>(h, Wag, bag, t, N);
    }
    // m = relu(t @ Wae + bae)
    {
        GemmParams p{};
        p.o[0] = { Wae, bae, nullptr, nullptr, m, 5 };
        gemm_fused<1><<<gg64, 256, GEMM_SMEM_BYTES>>>(t, p, N);
    }

    // pooling + MLP head
    zero_pool_kernel<<<(NGRAPH * D + 255) / 256, 256>>>(pmax, psum, cnt);
    {
        long long work = (long long)N * 32;
        pool_kernel<<<(unsigned)((work + 255) / 256), 256>>>(m, batch, pmax, psum, cnt, N);
    }
    mlp_kernel<<<NGRAPH, D>>>(pmax, psum, cnt, W1, b1, W2, b2, out);
}